// round 8
// baseline (speedup 1.0000x reference)
#include <cuda_runtime.h>
#include <cuda_fp16.h>
#include <cstdint>

// Problem: N=2048, D=128, k=4, T=0.5.
// rows (queries) = 4096, cols (keys) = 8192.
// sim = norm(z[0:4096]) @ norm(z_all)^T * 2 ; mask non-target diagonals;
// loss = mean(logsumexp - pos). Logits in [-2,2] -> no max subtraction.
//
// f16 plan (validated rel_err=0 in round 7): A = f16(2*log2(e) * zhat),
// B = f16(zhat); f16 accumulators give acc = 2*log2(e)*sim.
// exp term = h2exp2(acc); pos = acc * ln2; masked diag subtracts the SAME
// computed ex2 term (exact cancellation).

#define DIMK 128
#define SCALEA 2.885390081777927f     // 2 * log2(e)
#define LN2F 0.6931471805599453f

// ---------------- device scratch (no allocations allowed) -------------------
__device__ __half g_a16[4096 * 128];   // scaled normalized queries
__device__ __half g_b16[8192 * 128];   // normalized keys
__device__ float g_S[4096 * 32];       // [row][cg*2+wn] exp-sum partials
__device__ float g_pos[4096 * 32];     // [row][cg*2+wn] positive logit
__device__ unsigned int g_cnt;         // arrival counter (reset by last CTA)

__device__ __forceinline__ uint32_t smem_u32(const void* p) {
    uint32_t a;
    asm("{ .reg .u64 t; cvta.to.shared.u64 t, %1; cvt.u32.u64 %0, t; }"
        : "=r"(a) : "l"(p));
    return a;
}
__device__ __forceinline__ void ldsm_x4(uint32_t* r, uint32_t addr) {
    asm volatile("ldmatrix.sync.aligned.m8n8.x4.shared.b16 {%0,%1,%2,%3}, [%4];"
                 : "=r"(r[0]), "=r"(r[1]), "=r"(r[2]), "=r"(r[3]) : "r"(addr));
}
__device__ __forceinline__ void mma_h16(uint32_t* c, const uint32_t* a,
                                        uint32_t b0, uint32_t b1) {
    asm volatile(
        "mma.sync.aligned.m16n8k16.row.col.f16.f16.f16.f16 "
        "{%0,%1}, {%2,%3,%4,%5}, {%6,%7}, {%0,%1};"
        : "+r"(c[0]), "+r"(c[1])
        : "r"(a[0]), "r"(a[1]), "r"(a[2]), "r"(a[3]), "r"(b0), "r"(b1));
}

#define CP_ASYNC16(sm, gp) \
    asm volatile("cp.async.cg.shared.global [%0], [%1], 16;" :: "r"(sm), "l"(gp))
#define CP_COMMIT() asm volatile("cp.async.commit_group;" ::: "memory")
#define CP_WAIT_ALL() asm volatile("cp.async.wait_all;" ::: "memory")

// ---------------------------------------------------------------------------
// Kernel 1: L2-normalize 8192 rows -> f16 keys; first 4096 also scaled f16
// queries. 4 rows per warp. grid 256 x 256.
// ---------------------------------------------------------------------------
__global__ void normalize_kernel(const float* __restrict__ a1,
                                 const float* __restrict__ a2,
                                 const float* __restrict__ a3,
                                 const float* __restrict__ a4) {
    int w = threadIdx.x >> 5, lane = threadIdx.x & 31;
    int row0 = blockIdx.x * 32 + w * 4;
    float4 v[4];
    float ss[4];
#pragma unroll
    for (int i = 0; i < 4; i++) {
        int row = row0 + i;
        const float* src = (row < 2048) ? a1 : (row < 4096) ? a2
                          : (row < 6144) ? a3 : a4;
        v[i] = *(const float4*)(src + (row & 2047) * DIMK + lane * 4);
        ss[i] = v[i].x * v[i].x + v[i].y * v[i].y + v[i].z * v[i].z + v[i].w * v[i].w;
    }
#pragma unroll
    for (int off = 16; off; off >>= 1) {
#pragma unroll
        for (int i = 0; i < 4; i++) ss[i] += __shfl_xor_sync(~0u, ss[i], off);
    }
#pragma unroll
    for (int i = 0; i < 4; i++) {
        int row = row0 + i;
        float inv = 1.0f / fmaxf(sqrtf(ss[i]), 1e-8f);
        float x = v[i].x * inv, y = v[i].y * inv, z = v[i].z * inv, wv = v[i].w * inv;
        __half2 b0 = __float22half2_rn(make_float2(x, y));
        __half2 b1 = __float22half2_rn(make_float2(z, wv));
        uint2 st;
        st.x = *(uint32_t*)&b0;
        st.y = *(uint32_t*)&b1;
        ((uint2*)(g_b16 + row * DIMK))[lane] = st;
        if (row < 4096) {
            __half2 s0 = __float22half2_rn(make_float2(SCALEA * x, SCALEA * y));
            __half2 s1 = __float22half2_rn(make_float2(SCALEA * z, SCALEA * wv));
            uint2 sa;
            sa.x = *(uint32_t*)&s0;
            sa.y = *(uint32_t*)&s1;
            ((uint2*)(g_a16 + row * DIMK))[lane] = sa;
        }
    }
}

// ---------------------------------------------------------------------------
// Kernel 2: f16 HMMA GEMM (f16 acc) + fused exp epilogue + last-CTA finalize.
// CTA tile = 128 rows x 512 cols (8 subtiles of 64 cols), K=128 in one shot.
// 256 threads = 8 warps (4 M x 2 N), warp tile 32x32.
// XOR-swizzled SMEM (no padding): A 32KB + B 2x16KB = 64KB -> 3 CTAs/SM.
// grid = (32 row tiles, 16 col groups) = 512 CTAs.
// Swizzle: chunk c (16B) of row r stored at r*256 + ((c ^ (r&7))*16).
// ---------------------------------------------------------------------------
#define SM_A 0
#define SM_B0 32768
#define SM_B1 49152
#define SMEM_BYTES 65536

__global__ void __launch_bounds__(256, 3) sim_kernel(float* __restrict__ out) {
    extern __shared__ char smem[];
    uint32_t sb = smem_u32(smem);
    __shared__ int sLast;
    __shared__ float wsum[8];

    int tid = threadIdx.x;
    int lane = tid & 31;
    int w = tid >> 5;
    int wm = w & 3;        // M warp (rows wm*32..+31)
    int wn = w >> 2;       // N warp (cols wn*32..+31 of the 64-col subtile)
    int row0 = blockIdx.x * 128;
    int cg = blockIdx.y;                  // cols [cg*512, cg*512+512)

    // ---- prologue: A (128 rows) + B subtile 0 (64 rows) ----
    {
        int r = tid >> 1;                  // A: 8 iters of 256 over 2048 vecs
#pragma unroll
        for (int it = 0; it < 8; it++) {
            int idx = it * 256 + tid;
            int rr = idx >> 4, c = idx & 15;
            CP_ASYNC16(sb + SM_A + rr * 256 + ((c ^ (rr & 7)) << 4),
                       (const char*)(g_a16 + (row0 + rr) * DIMK + c * 8));
        }
        (void)r;
#pragma unroll
        for (int it = 0; it < 4; it++) {   // B: 1024 vecs
            int idx = it * 256 + tid;
            int rr = idx >> 4, c = idx & 15;
            CP_ASYNC16(sb + SM_B0 + rr * 256 + ((c ^ (rr & 7)) << 4),
                       (const char*)(g_b16 + (cg * 512 + rr) * DIMK + c * 8));
        }
        CP_COMMIT();
    }

    // ---- ldmatrix lane bases (swizzled) ----
    int arow = wm * 32 + ((lane >> 3) & 1) * 8 + (lane & 7);  // mi adds +16
    int koctA = lane >> 4;                                    // 0/1
    int r7A = arow & 7;
    uint32_t baseA0 = sb + SM_A + arow * 256;
    uint32_t baseA1 = baseA0 + 16 * 256;

    int brow = wn * 32 + ((lane >> 4) & 1) * 8 + (lane & 7);  // nset adds +16
    int koctB = (lane >> 3) & 1;
    int r7B = brow & 7;
    uint32_t baseBrow0 = brow * 256;
    uint32_t baseBrow1 = baseBrow0 + 16 * 256;

    int qrow = lane >> 2;          // 0..7
    // ---- per-row diagonal bookkeeping ----
    int half = row0 >> 11;
    int cblk = cg >> 2;
    bool tgt = (cblk == 1 - half);
    int dl0 = (row0 & 2047) - (cg & 3) * 512;

    int dcol[4], rloc[4];
#pragma unroll
    for (int mi = 0; mi < 2; mi++)
#pragma unroll
        for (int h = 0; h < 2; h++) {
            int i = mi * 2 + h;
            rloc[i] = wm * 32 + mi * 16 + qrow + 8 * h;
            dcol[i] = dl0 + rloc[i];      // diag col within CTA's 512 cols
        }

    float sumReg[4] = {0.f, 0.f, 0.f, 0.f};
    float posReg[4] = {0.f, 0.f, 0.f, 0.f};

    for (int ct = 0; ct < 8; ct++) {
        CP_WAIT_ALL();
        __syncthreads();

        if (ct < 7) {                     // prefetch B(ct+1), overlapped
            uint32_t dstb = sb + (((ct + 1) & 1) ? SM_B1 : SM_B0);
            int gcol = cg * 512 + (ct + 1) * 64;
#pragma unroll
            for (int it = 0; it < 4; it++) {
                int idx = it * 256 + tid;
                int rr = idx >> 4, c = idx & 15;
                CP_ASYNC16(dstb + rr * 256 + ((c ^ (rr & 7)) << 4),
                           (const char*)(g_b16 + (gcol + rr) * DIMK + c * 8));
            }
            CP_COMMIT();
        }

        uint32_t bufB = sb + ((ct & 1) ? SM_B1 : SM_B0);

        uint32_t acc[2][4][2];            // [mi][n8 frag][c-pair]
#pragma unroll
        for (int mi = 0; mi < 2; mi++)
#pragma unroll
            for (int ni = 0; ni < 4; ni++) {
                acc[mi][ni][0] = 0u;
                acc[mi][ni][1] = 0u;
            }

#pragma unroll
        for (int ks = 0; ks < 8; ks++) {
            int gA = 2 * ks + koctA;
            uint32_t offA = (uint32_t)((gA ^ r7A) << 4);
            int gB = 2 * ks + koctB;
            uint32_t offB = (uint32_t)((gB ^ r7B) << 4);
            uint32_t a0[4], a1[4], b0[4], b1[4];
            ldsm_x4(a0, baseA0 + offA);
            ldsm_x4(a1, baseA1 + offA);
            ldsm_x4(b0, bufB + baseBrow0 + offB);  // n frags 0,1
            ldsm_x4(b1, bufB + baseBrow1 + offB);  // n frags 2,3
            mma_h16(acc[0][0], a0, b0[0], b0[1]);
            mma_h16(acc[0][1], a0, b0[2], b0[3]);
            mma_h16(acc[0][2], a0, b1[0], b1[1]);
            mma_h16(acc[0][3], a0, b1[2], b1[3]);
            mma_h16(acc[1][0], a1, b0[0], b0[1]);
            mma_h16(acc[1][1], a1, b0[2], b0[3]);
            mma_h16(acc[1][2], a1, b1[0], b1[1]);
            mma_h16(acc[1][3], a1, b1[2], b1[3]);
        }

        // ---- epilogue: packed ex2 + tree sum + lazy diag fixup ----
#pragma unroll
        for (int mi = 0; mi < 2; mi++)
#pragma unroll
            for (int h = 0; h < 2; h++) {
                int i = mi * 2 + h;
                __half2 e0 = h2exp2(*(__half2*)&acc[mi][0][h]);
                __half2 e1 = h2exp2(*(__half2*)&acc[mi][1][h]);
                __half2 e2 = h2exp2(*(__half2*)&acc[mi][2][h]);
                __half2 e3 = h2exp2(*(__half2*)&acc[mi][3][h]);
                __half2 t = __hadd2(__hadd2(e0, e1), __hadd2(e2, e3));
                float2 f = __half22float2(t);
                sumReg[i] += f.x + f.y;
                int d = dcol[i];
                if ((unsigned)d < 512u && (d >> 6) == ct
                    && ((d >> 5) & 1) == wn
                    && ((d & 7) >> 1) == (lane & 3)) {
                    int nid = (d & 31) >> 3;
                    __half2 av = *(__half2*)&acc[mi][nid][h];
                    if (tgt) {
                        float a = (d & 1) ? __high2float(av) : __low2float(av);
                        posReg[i] += a * LN2F;
                    } else {
                        __half2 ev = h2exp2(av);         // same term as summed
                        sumReg[i] -= (d & 1) ? __high2float(ev) : __low2float(ev);
                    }
                }
            }
    }

    // ---- per-row reduce across 4 col-lanes; write global partials ----
#pragma unroll
    for (int i = 0; i < 4; i++) {
        sumReg[i] += __shfl_xor_sync(~0u, sumReg[i], 1);
        sumReg[i] += __shfl_xor_sync(~0u, sumReg[i], 2);
        posReg[i] += __shfl_xor_sync(~0u, posReg[i], 1);
        posReg[i] += __shfl_xor_sync(~0u, posReg[i], 2);
    }
    if ((lane & 3) == 0) {
#pragma unroll
        for (int i = 0; i < 4; i++) {
            int row = row0 + rloc[i];
            g_S[row * 32 + cg * 2 + wn] = sumReg[i];
            g_pos[row * 32 + cg * 2 + wn] = posReg[i];
        }
    }

    // ---- last-CTA finalize (deterministic) ----
    __threadfence();
    __syncthreads();
    if (tid == 0) sLast = (atomicAdd(&g_cnt, 1u) == 511u);
    __syncthreads();
    if (sLast) {
        __threadfence();   // acquire side
        float local = 0.f;
        for (int r = tid; r < 4096; r += 256) {
            const float4* s4 = (const float4*)(g_S + r * 32);
            const float4* p4 = (const float4*)(g_pos + r * 32);
            float S = 0.f, p = 0.f;
#pragma unroll
            for (int q = 0; q < 8; q++) {
                float4 x = s4[q], y = p4[q];
                S += (x.x + x.y) + (x.z + x.w);
                p += (y.x + y.y) + (y.z + y.w);
            }
            local += logf(S) - p;
        }
#pragma unroll
        for (int off = 16; off; off >>= 1) local += __shfl_xor_sync(~0u, local, off);
        if (lane == 0) wsum[tid >> 5] = local;
        __syncthreads();
        if (tid < 32) {
            float t = (tid < 8) ? wsum[tid] : 0.f;
#pragma unroll
            for (int off = 4; off; off >>= 1) t += __shfl_xor_sync(~0u, t, off);
            if (tid == 0) {
                out[0] = t / 4096.f;
                g_cnt = 0;               // reset for next graph replay
            }
        }
    }
}

// ---------------------------------------------------------------------------
extern "C" void kernel_launch(void* const* d_in, const int* in_sizes, int n_in,
                              void* d_out, int out_size) {
    const float* a1 = (const float*)d_in[0];
    const float* a2 = (const float*)d_in[1];
    const float* a3 = (const float*)d_in[2];
    const float* a4 = (const float*)d_in[3];

    normalize_kernel<<<256, 256>>>(a1, a2, a3, a4);

    cudaFuncSetAttribute(sim_kernel, cudaFuncAttributeMaxDynamicSharedMemorySize,
                         SMEM_BYTES);
    dim3 grid(32, 16);
    sim_kernel<<<grid, 256, SMEM_BYTES>>>((float*)d_out);
}

// round 9
// speedup vs baseline: 1.3920x; 1.3920x over previous
#include <cuda_runtime.h>
#include <cuda_fp16.h>
#include <cstdint>

// Problem: N=2048, D=128, k=4, T=0.5.
// rows (queries) = 4096, cols (keys) = 8192.
// sim = norm(z[0:4096]) @ norm(z_all)^T * 2 ; mask non-target diagonals;
// loss = mean(logsumexp - pos). Logits in [-2,2] -> no max subtraction.
//
// Single fused kernel: normalize -> grid barrier -> f16 HMMA GEMM (fp32 acc)
// -> fused exp epilogue -> last-CTA finalize. 256 CTAs at 2/SM (capacity
// 296) are co-resident, so the counter grid-barrier cannot deadlock.
// A operand = f16(2*log2(e) * zhat)  ->  acc = 2*log2(e)*sim,
// exp term = ex2(acc), pos = acc*ln2, masked diag subtracts the SAME term.

#define DIMK 128
#define SCALEA 2.885390081777927f     // 2 * log2(e)
#define LN2F 0.6931471805599453f

// ---------------- device scratch (no allocations allowed) -------------------
__device__ __half g_a16[4096 * 128];   // scaled normalized queries
__device__ __half g_b16[8192 * 128];   // normalized keys
__device__ float g_S[4096 * 8];        // [row][cg] exp-sum partials
__device__ float g_pos[4096 * 8];      // [row][cg] positive logit
__device__ unsigned int g_bar;         // grid barrier (normalize done)
__device__ unsigned int g_cnt;         // finalize arrival counter

__device__ __forceinline__ uint32_t smem_u32(const void* p) {
    uint32_t a;
    asm("{ .reg .u64 t; cvta.to.shared.u64 t, %1; cvt.u32.u64 %0, t; }"
        : "=r"(a) : "l"(p));
    return a;
}
__device__ __forceinline__ float ex2(float x) {
    float y;
    asm("ex2.approx.ftz.f32 %0, %1;" : "=f"(y) : "f"(x));
    return y;
}
__device__ __forceinline__ void ldsm_x4(uint32_t* r, uint32_t addr) {
    asm volatile("ldmatrix.sync.aligned.m8n8.x4.shared.b16 {%0,%1,%2,%3}, [%4];"
                 : "=r"(r[0]), "=r"(r[1]), "=r"(r[2]), "=r"(r[3]) : "r"(addr));
}
__device__ __forceinline__ void mma16816(float* c, const uint32_t* a,
                                         uint32_t b0, uint32_t b1) {
    asm volatile(
        "mma.sync.aligned.m16n8k16.row.col.f32.f16.f16.f32 "
        "{%0,%1,%2,%3}, {%4,%5,%6,%7}, {%8,%9}, {%0,%1,%2,%3};"
        : "+f"(c[0]), "+f"(c[1]), "+f"(c[2]), "+f"(c[3])
        : "r"(a[0]), "r"(a[1]), "r"(a[2]), "r"(a[3]), "r"(b0), "r"(b1));
}

#define CP_ASYNC16(sm, gp) \
    asm volatile("cp.async.cg.shared.global [%0], [%1], 16;" :: "r"(sm), "l"(gp))
#define CP_COMMIT() asm volatile("cp.async.commit_group;" ::: "memory")
#define CP_WAIT_ALL() asm volatile("cp.async.wait_all;" ::: "memory")

// ---------------------------------------------------------------------------
// SMEM layout (padded stride 272B, conflict-free ldmatrix; proven in R4/R7)
// ---------------------------------------------------------------------------
#define TSTRIDE 272
#define SM_A 0
#define SM_B0 (128 * TSTRIDE)       // 34816
#define SM_B1 (2 * 128 * TSTRIDE)   // 69632
#define SMEM_BYTES (3 * 128 * TSTRIDE)  // 104448 -> 2 CTA/SM

__device__ __forceinline__ void issue_tile_load(uint32_t sb, int sm_off,
                                                const __half* src, int grow0,
                                                int tid) {
#pragma unroll
    for (int it = 0; it < 8; it++) {
        int idx = it * 256 + tid;           // 2048 16B vectors
        int r = idx >> 4, g = idx & 15;
        CP_ASYNC16(sb + sm_off + r * TSTRIDE + g * 16,
                   (const char*)(src + (grow0 + r) * DIMK + g * 8));
    }
}

__global__ void __launch_bounds__(256, 2) fused_kernel(
    const float* __restrict__ a1, const float* __restrict__ a2,
    const float* __restrict__ a3, const float* __restrict__ a4,
    float* __restrict__ out) {
    extern __shared__ char smem[];
    uint32_t sb = smem_u32(smem);
    __shared__ int sLast;
    __shared__ float wsum[8];

    int tid = threadIdx.x;
    int lane = tid & 31;
    int w = tid >> 5;
    int ctaid = blockIdx.x * 8 + blockIdx.y;     // 0..255

    // ================= Phase 0: normalize 32 rows per CTA ==================
    {
        int row0n = ctaid * 32 + w * 4;          // 4 rows per warp
        float4 v[4];
        float ss[4];
#pragma unroll
        for (int i = 0; i < 4; i++) {
            int row = row0n + i;
            const float* src = (row < 2048) ? a1 : (row < 4096) ? a2
                              : (row < 6144) ? a3 : a4;
            v[i] = *(const float4*)(src + (row & 2047) * DIMK + lane * 4);
            ss[i] = v[i].x * v[i].x + v[i].y * v[i].y + v[i].z * v[i].z
                  + v[i].w * v[i].w;
        }
#pragma unroll
        for (int off = 16; off; off >>= 1) {
#pragma unroll
            for (int i = 0; i < 4; i++) ss[i] += __shfl_xor_sync(~0u, ss[i], off);
        }
#pragma unroll
        for (int i = 0; i < 4; i++) {
            int row = row0n + i;
            float inv = 1.0f / fmaxf(sqrtf(ss[i]), 1e-8f);
            float x = v[i].x * inv, y = v[i].y * inv;
            float z = v[i].z * inv, wv = v[i].w * inv;
            __half2 b0 = __float22half2_rn(make_float2(x, y));
            __half2 b1 = __float22half2_rn(make_float2(z, wv));
            uint2 st;
            st.x = *(uint32_t*)&b0;
            st.y = *(uint32_t*)&b1;
            ((uint2*)(g_b16 + row * DIMK))[lane] = st;
            if (row < 4096) {
                __half2 s0 = __float22half2_rn(make_float2(SCALEA * x, SCALEA * y));
                __half2 s1 = __float22half2_rn(make_float2(SCALEA * z, SCALEA * wv));
                uint2 sa;
                sa.x = *(uint32_t*)&s0;
                sa.y = *(uint32_t*)&s1;
                ((uint2*)(g_a16 + row * DIMK))[lane] = sa;
            }
        }
    }

    // ================= Phase 1: grid barrier (all CTAs co-resident) ========
    __threadfence();
    __syncthreads();
    if (tid == 0) {
        atomicAdd(&g_bar, 1u);
        while (*(volatile unsigned int*)&g_bar < 256u) { }
    }
    __syncthreads();
    __threadfence();

    // ================= Phase 2: GEMM + epilogue =============================
    int wm = w & 3;        // M warp (rows wm*32..+31)
    int wn = w >> 2;       // N warp (cols wn*64..+63)
    int row0 = blockIdx.x * 128;
    int cg = blockIdx.y;                  // cols [cg*1024, cg*1024+1024)

    issue_tile_load(sb, SM_A, g_a16, row0, tid);
    issue_tile_load(sb, SM_B0, g_b16, cg * 1024, tid);
    CP_COMMIT();

    int arow = wm * 32 + ((lane >> 3) & 1) * 8 + (lane & 7);
    int akoct = (lane >> 4) * 8;
    uint32_t baseA = sb + SM_A + arow * TSTRIDE + akoct * 2;
    int brow = wn * 64 + ((lane >> 4) & 1) * 8 + (lane & 7);
    int bkoct = ((lane >> 3) & 1) * 8;
    uint32_t baseBoff = brow * TSTRIDE + bkoct * 2;

    int qrow = lane >> 2;          // 0..7
    int half = row0 >> 11;
    int cblk = cg >> 1;
    bool tgt = (cblk == 1 - half);
    int dl0 = (row0 & 2047) - (cg & 1) * 1024;

    int nid[4], c_id[4], dsub[4], rloc[4];
    bool fix[4];
#pragma unroll
    for (int mi = 0; mi < 2; mi++)
#pragma unroll
        for (int h = 0; h < 2; h++) {
            int i = mi * 2 + h;
            int row_local = wm * 32 + mi * 16 + qrow + 8 * h;
            rloc[i] = row_local;
            int d = dl0 + row_local;
            dsub[i] = d >> 7;
            nid[i] = (d & 63) >> 3;
            c_id[i] = 2 * h + (d & 1);
            fix[i] = (d >= 0) && (d < 1024)
                   && (((d >> 6) & 1) == wn)
                   && (((d & 7) >> 1) == (lane & 3));
        }

    float sumReg[4] = {0.f, 0.f, 0.f, 0.f};
    float posReg[4] = {0.f, 0.f, 0.f, 0.f};

    for (int ct = 0; ct < 8; ct++) {
        CP_WAIT_ALL();
        __syncthreads();

        if (ct < 7) {
            issue_tile_load(sb, ((ct + 1) & 1) ? SM_B1 : SM_B0,
                            g_b16, cg * 1024 + (ct + 1) * 128, tid);
            CP_COMMIT();
        }

        uint32_t baseB = sb + ((ct & 1) ? SM_B1 : SM_B0) + baseBoff;

        float acc[2][8][4];
#pragma unroll
        for (int mi = 0; mi < 2; mi++)
#pragma unroll
            for (int ni = 0; ni < 8; ni++)
#pragma unroll
                for (int c = 0; c < 4; c++) acc[mi][ni][c] = 0.f;

#pragma unroll
        for (int ks = 0; ks < 8; ks++) {
            uint32_t a[2][4];
            ldsm_x4(a[0], baseA + ks * 32);
            ldsm_x4(a[1], baseA + 16 * TSTRIDE + ks * 32);
            uint32_t b[4][4];
#pragma unroll
            for (int nip = 0; nip < 4; nip++)
                ldsm_x4(b[nip], baseB + nip * 16 * TSTRIDE + ks * 32);
#pragma unroll
            for (int mi = 0; mi < 2; mi++)
#pragma unroll
                for (int nip = 0; nip < 4; nip++) {
                    mma16816(acc[mi][2 * nip + 0], a[mi], b[nip][0], b[nip][1]);
                    mma16816(acc[mi][2 * nip + 1], a[mi], b[nip][2], b[nip][3]);
                }
        }

        // ---- epilogue: ex2-sum (scale pre-folded into A) + diag fixup ----
#pragma unroll
        for (int mi = 0; mi < 2; mi++)
#pragma unroll
            for (int h = 0; h < 2; h++) {
                int i = mi * 2 + h;
                float s = 0.f;
#pragma unroll
                for (int ni = 0; ni < 8; ni++) {
                    s += ex2(acc[mi][ni][2 * h + 0]);
                    s += ex2(acc[mi][ni][2 * h + 1]);
                }
                sumReg[i] += s;
                if (fix[i] && dsub[i] == ct) {
                    float vd = acc[mi][nid[i]][c_id[i]];
                    if (tgt) posReg[i] += vd * LN2F;       // pos = acc*ln2
                    else sumReg[i] -= ex2(vd);             // same term: cancel
                }
            }
    }

    // ---- per-row reduce across the 4 col-lanes; write global partials ----
#pragma unroll
    for (int i = 0; i < 4; i++) {
        sumReg[i] += __shfl_xor_sync(~0u, sumReg[i], 1);
        sumReg[i] += __shfl_xor_sync(~0u, sumReg[i], 2);
        posReg[i] += __shfl_xor_sync(~0u, posReg[i], 1);
        posReg[i] += __shfl_xor_sync(~0u, posReg[i], 2);
    }
    // combine the two N warps via SMEM (reuse B0 buffer region)
    float* sS = (float*)(smem + SM_B0);
    float* sP = (float*)(smem + SM_B0 + 1024);
    __syncthreads();
    if ((lane & 3) == 0 && wn == 1) {
#pragma unroll
        for (int i = 0; i < 4; i++) {
            sS[rloc[i]] = sumReg[i];
            sP[rloc[i]] = posReg[i];
        }
    }
    __syncthreads();
    if ((lane & 3) == 0 && wn == 0) {
#pragma unroll
        for (int i = 0; i < 4; i++) {
            int row = row0 + rloc[i];
            g_S[row * 8 + cg] = sumReg[i] + sS[rloc[i]];
            g_pos[row * 8 + cg] = posReg[i] + sP[rloc[i]];
        }
    }

    // ================= Phase 3: last-CTA finalize ===========================
    __threadfence();
    __syncthreads();
    if (tid == 0) sLast = (atomicAdd(&g_cnt, 1u) == 255u);
    __syncthreads();
    if (sLast) {
        __threadfence();   // acquire side
        float local = 0.f;
        for (int r = tid; r < 4096; r += 256) {
            const float4* s4 = (const float4*)(g_S + r * 8);
            const float4* p4 = (const float4*)(g_pos + r * 8);
            float4 x0 = s4[0], x1 = s4[1], y0 = p4[0], y1 = p4[1];
            float S = (x0.x + x0.y) + (x0.z + x0.w) + (x1.x + x1.y) + (x1.z + x1.w);
            float p = (y0.x + y0.y) + (y0.z + y0.w) + (y1.x + y1.y) + (y1.z + y1.w);
            local += logf(S) - p;
        }
#pragma unroll
        for (int off = 16; off; off >>= 1) local += __shfl_xor_sync(~0u, local, off);
        if (lane == 0) wsum[tid >> 5] = local;
        __syncthreads();
        if (tid < 32) {
            float t = (tid < 8) ? wsum[tid] : 0.f;
#pragma unroll
            for (int off = 4; off; off >>= 1) t += __shfl_xor_sync(~0u, t, off);
            if (tid == 0) {
                out[0] = t / 4096.f;
                g_cnt = 0;               // reset for next graph replay
                g_bar = 0;
            }
        }
    }
}

// ---------------------------------------------------------------------------
extern "C" void kernel_launch(void* const* d_in, const int* in_sizes, int n_in,
                              void* d_out, int out_size) {
    const float* a1 = (const float*)d_in[0];
    const float* a2 = (const float*)d_in[1];
    const float* a3 = (const float*)d_in[2];
    const float* a4 = (const float*)d_in[3];

    cudaFuncSetAttribute(fused_kernel, cudaFuncAttributeMaxDynamicSharedMemorySize,
                         SMEM_BYTES);
    dim3 grid(32, 8);
    fused_kernel<<<grid, 256, SMEM_BYTES>>>(a1, a2, a3, a4, (float*)d_out);
}